// round 2
// baseline (speedup 1.0000x reference)
#include <cuda_runtime.h>

// ---------------------------------------------------------------------------
// Fused IGCNet conv: 3 launches, each fully fuses
//   edge MLP (gather+concat -> 40->64 relu -> 64->32 relu)
//   segment max (contiguous: node i owns edges [16i,16i+16))
//   node MLP (concat(x,aggr)=64 -> 64 relu -> 16 relu), norm clip, concat x[:,:16]
// Block = 256 threads = 16 nodes = 256 edges.
// NOTE: edge_index is int32 (JAX default, x64 disabled despite jnp.int64 ask).
// ---------------------------------------------------------------------------

#define NMAX 100000
__device__ float g_buf0[(size_t)NMAX * 32];
__device__ float g_buf1[(size_t)NMAX * 32];

// shared memory layout (float offsets)
#define OFF_W1T   0                 // [40][64]  w1_1 transposed
#define OFF_B1    2560              // [64]
#define OFF_W2T   2624              // [64][32]  w1_2 transposed
#define OFF_B2    4672              // [32]
#define OFF_W3T   4704              // [64][64]  w2_1 transposed
#define OFF_B3    8800              // [64]
#define OFF_W4T   8864              // [64][16]  w2_2 transposed
#define OFF_B4    9888              // [16]
#define OFF_XIN   9904              // [16][64]  per-node [x_i(32) | aggr(32)]
#define OFF_U     10928             // union: A[40][256] then H[64][HS] then hid[16][64]
#define HS        260               // H row stride (conflict-free .128 stores)
#define SMEM_FLOATS (OFF_U + 64 * HS)

__global__ void __launch_bounds__(256, 2) conv_kernel(
    const float* __restrict__ h_in, float* __restrict__ h_out,
    const int* __restrict__ src, const float* __restrict__ edge_attr,
    const float* __restrict__ w11, const float* __restrict__ b11,
    const float* __restrict__ w12, const float* __restrict__ b12,
    const float* __restrict__ w21, const float* __restrict__ b21,
    const float* __restrict__ w22, const float* __restrict__ b22)
{
    extern __shared__ float s[];
    const int tid = threadIdx.x;

    // ---- stage weights (transposed so the k-loop reads contiguous rows) ----
    for (int i = tid; i < 2560; i += 256) { int k = i >> 6, h = i & 63; s[OFF_W1T + k * 64 + h] = w11[h * 40 + k]; }
    for (int i = tid; i < 2048; i += 256) { int k = i >> 5, o = i & 31; s[OFF_W2T + k * 32 + o] = w12[o * 64 + k]; }
    for (int i = tid; i < 4096; i += 256) { int k = i >> 6, h = i & 63; s[OFF_W3T + k * 64 + h] = w21[h * 64 + k]; }
    for (int i = tid; i < 1024; i += 256) { int k = i >> 4, o = i & 15; s[OFF_W4T + k * 16 + o] = w22[o * 64 + k]; }
    if (tid < 64) s[OFF_B1 + tid] = b11[tid];
    if (tid < 32) s[OFF_B2 + tid] = b12[tid];
    if (tid < 64) s[OFF_B3 + tid] = b21[tid];
    if (tid < 16) s[OFF_B4 + tid] = b22[tid];

    const int n0 = blockIdx.x * 16;

    // ---- gather: A[k][e] tile, k-major, stride 256 (thread = one edge) ----
    {
        const long long eg = (long long)blockIdx.x * 256 + tid;
        const int si = src[eg];
        const float4* xr = (const float4*)(h_in + (size_t)si * 32);
        #pragma unroll
        for (int j = 0; j < 8; j++) {
            float4 v = xr[j];
            s[OFF_U + (4 * j + 0) * 256 + tid] = v.x;
            s[OFF_U + (4 * j + 1) * 256 + tid] = v.y;
            s[OFF_U + (4 * j + 2) * 256 + tid] = v.z;
            s[OFF_U + (4 * j + 3) * 256 + tid] = v.w;
        }
        const float4* ar = (const float4*)(edge_attr + (size_t)eg * 8);
        #pragma unroll
        for (int j = 0; j < 2; j++) {
            float4 v = ar[j];
            s[OFF_U + (32 + 4 * j + 0) * 256 + tid] = v.x;
            s[OFF_U + (32 + 4 * j + 1) * 256 + tid] = v.y;
            s[OFF_U + (32 + 4 * j + 2) * 256 + tid] = v.z;
            s[OFF_U + (32 + 4 * j + 3) * 256 + tid] = v.w;
        }
        if (tid < 128) {  // destination-node features -> Xin[:, 0:32]
            int nd = tid >> 3, q = tid & 7;
            float4 v = *(const float4*)(h_in + (size_t)(n0 + nd) * 32 + q * 4);
            *(float4*)&s[OFF_XIN + nd * 64 + q * 4] = v;
        }
    }
    __syncthreads();

    // ---- GEMM1: [256 edges, 40] x [40, 64] -> hidden, 8x8 register tile ----
    const int eg = tid >> 3;         // 0..31, edges eg*8..eg*8+7
    const int hg = tid & 7;          // 0..7,  hidden hg*8..hg*8+7
    const int e0 = eg * 8, h0 = hg * 8;
    float acc[8][8];
    #pragma unroll
    for (int i = 0; i < 8; i++) {
        float b = s[OFF_B1 + h0 + i];
        #pragma unroll
        for (int j = 0; j < 8; j++) acc[i][j] = b;
    }
    #pragma unroll 4
    for (int k = 0; k < 40; k++) {
        const float4 a0 = *(const float4*)&s[OFF_U + k * 256 + e0];
        const float4 a1 = *(const float4*)&s[OFF_U + k * 256 + e0 + 4];
        const float4 q0 = *(const float4*)&s[OFF_W1T + k * 64 + h0];
        const float4 q1 = *(const float4*)&s[OFF_W1T + k * 64 + h0 + 4];
        const float aa[8] = {a0.x, a0.y, a0.z, a0.w, a1.x, a1.y, a1.z, a1.w};
        const float ww[8] = {q0.x, q0.y, q0.z, q0.w, q1.x, q1.y, q1.z, q1.w};
        #pragma unroll
        for (int i = 0; i < 8; i++)
            #pragma unroll
            for (int j = 0; j < 8; j++)
                acc[i][j] = fmaf(ww[i], aa[j], acc[i][j]);
    }
    __syncthreads();   // all A reads done; U is reused as H
    #pragma unroll
    for (int i = 0; i < 8; i++) {
        float4 v0 = make_float4(fmaxf(acc[i][0], 0.f), fmaxf(acc[i][1], 0.f),
                                fmaxf(acc[i][2], 0.f), fmaxf(acc[i][3], 0.f));
        float4 v1 = make_float4(fmaxf(acc[i][4], 0.f), fmaxf(acc[i][5], 0.f),
                                fmaxf(acc[i][6], 0.f), fmaxf(acc[i][7], 0.f));
        *(float4*)&s[OFF_U + (h0 + i) * HS + e0]     = v0;
        *(float4*)&s[OFF_U + (h0 + i) * HS + e0 + 4] = v1;
    }
    __syncthreads();

    // ---- GEMM2: [256, 64] x [64, 32] -> msg, relu, max over 16-edge segs ---
    const int og = tid & 7, o0 = og * 4;   // same eg as GEMM1
    float acc2[8][4];
    #pragma unroll
    for (int c = 0; c < 4; c++) {
        float b = s[OFF_B2 + o0 + c];
        #pragma unroll
        for (int j = 0; j < 8; j++) acc2[j][c] = b;
    }
    #pragma unroll 4
    for (int k = 0; k < 64; k++) {
        const float4 hA = *(const float4*)&s[OFF_U + k * HS + e0];
        const float4 hB = *(const float4*)&s[OFF_U + k * HS + e0 + 4];
        const float4 wv = *(const float4*)&s[OFF_W2T + k * 32 + o0];
        const float hh[8] = {hA.x, hA.y, hA.z, hA.w, hB.x, hB.y, hB.z, hB.w};
        const float wwv[4] = {wv.x, wv.y, wv.z, wv.w};
        #pragma unroll
        for (int j = 0; j < 8; j++)
            #pragma unroll
            for (int c = 0; c < 4; c++)
                acc2[j][c] = fmaf(hh[j], wwv[c], acc2[j][c]);
    }
    // relu + max over this thread's 8 edges (relu folds into max with 0 init)
    float mx[4] = {0.f, 0.f, 0.f, 0.f};
    #pragma unroll
    for (int j = 0; j < 8; j++)
        #pragma unroll
        for (int c = 0; c < 4; c++)
            mx[c] = fmaxf(mx[c], acc2[j][c]);
    // combine with partner (tid^8 shares the other 8 edges of this node)
    #pragma unroll
    for (int c = 0; c < 4; c++)
        mx[c] = fmaxf(mx[c], __shfl_xor_sync(0xffffffffu, mx[c], 8));
    if (!(eg & 1)) {
        int nd = eg >> 1;
        *(float4*)&s[OFF_XIN + nd * 64 + 32 + o0] = make_float4(mx[0], mx[1], mx[2], mx[3]);
    }
    __syncthreads();   // Xin complete; H dead -> U reused as hid

    // ---- node MLP: warp w handles nodes 2w, 2w+1 ----
    {
        const int wrp = tid >> 5, lane = tid & 31;
        const int nd = 2 * wrp + (lane >> 4);
        const int ll = lane & 15;
        float ha[4];
        #pragma unroll
        for (int t = 0; t < 4; t++) ha[t] = s[OFF_B3 + ll + 16 * t];
        #pragma unroll 8
        for (int k = 0; k < 64; k++) {
            const float xv = s[OFF_XIN + nd * 64 + k];
            #pragma unroll
            for (int t = 0; t < 4; t++)
                ha[t] = fmaf(xv, s[OFF_W3T + k * 64 + ll + 16 * t], ha[t]);
        }
        #pragma unroll
        for (int t = 0; t < 4; t++)
            s[OFF_U + nd * 64 + ll + 16 * t] = fmaxf(ha[t], 0.f);
        __syncwarp();
        float a3 = s[OFF_B4 + ll];
        #pragma unroll 8
        for (int k = 0; k < 64; k++)
            a3 = fmaf(s[OFF_U + nd * 64 + k], s[OFF_W4T + k * 16 + ll], a3);
        float v = fmaxf(a3, 0.f);
        // norm clip over the 16 outputs of this node (16-lane subgroup)
        float ss = v * v;
        ss += __shfl_xor_sync(0xffffffffu, ss, 1);
        ss += __shfl_xor_sync(0xffffffffu, ss, 2);
        ss += __shfl_xor_sync(0xffffffffu, ss, 4);
        ss += __shfl_xor_sync(0xffffffffu, ss, 8);
        const float sn = sqrtf(ss);
        if (sn > 1.f) v = v / sn;
        const size_t ng = (size_t)(n0 + nd);
        h_out[ng * 32 + ll]      = v;
        h_out[ng * 32 + 16 + ll] = s[OFF_XIN + nd * 64 + ll];  // x[:, :16]
    }
}

extern "C" void kernel_launch(void* const* d_in, const int* in_sizes, int n_in,
                              void* d_out, int out_size)
{
    const float* x     = (const float*)d_in[0];
    const int*   eidx  = (const int*)d_in[1];     // [2, E] int32 (JAX default)
    const float* eattr = (const float*)d_in[2];
    const float* w11 = (const float*)d_in[3];
    const float* b11 = (const float*)d_in[4];
    const float* w12 = (const float*)d_in[5];
    const float* b12 = (const float*)d_in[6];
    const float* w21 = (const float*)d_in[7];
    const float* b21 = (const float*)d_in[8];
    const float* w22 = (const float*)d_in[9];
    const float* b22 = (const float*)d_in[10];

    const int nN = in_sizes[0] / 32;          // 100000
    const int* srcp = eidx;                   // row 0 = src
    const int grid = nN / 16;                 // 6250 blocks (16 nodes each)
    const size_t smem = (size_t)SMEM_FLOATS * sizeof(float);

    cudaFuncSetAttribute(conv_kernel, cudaFuncAttributeMaxDynamicSharedMemorySize, (int)smem);

    float *b0, *b1;
    cudaGetSymbolAddress((void**)&b0, g_buf0);
    cudaGetSymbolAddress((void**)&b1, g_buf1);

    conv_kernel<<<grid, 256, smem>>>(x,  b0, srcp, eattr, w11, b11, w12, b12, w21, b21, w22, b22);
    conv_kernel<<<grid, 256, smem>>>(b0, b1, srcp, eattr, w11, b11, w12, b12, w21, b21, w22, b22);
    conv_kernel<<<grid, 256, smem>>>(b1, (float*)d_out, srcp, eattr, w11, b11, w12, b12, w21, b21, w22, b22);
}